// round 2
// baseline (speedup 1.0000x reference)
#include <cuda_runtime.h>
#include <math.h>

#define NN 32768
#define NE 49152
#define NB 1024
#define DD 64

// ---------------- device scratch (no allocations allowed) ----------------
__device__ float g_h1[NE * 128];                 // edge MLP hidden   (25 MB)
__device__ float g_W[(size_t)NE * 4096];         // edge weights      (805 MB)
__device__ float g_out[NN * DD];                 // node features / GRU h
__device__ float g_m[NN * DD];                   // conv output m
__device__ float g_agg[NN * DD];                 // message accumulator
__device__ float g_cnt[NN];                      // in-degree (float)
__device__ int   g_gcnt[NB];                     // nodes per graph
__device__ int   g_gptr[NB + 1];                 // CSR over sorted batch
__device__ float g_qstar[NB * 2 * DD];
__device__ float g_hl[NB * DD];
__device__ float g_cl[NB * DD];
__device__ float g_e[NN];                        // attention logits / exp

__device__ __forceinline__ float sigmoidf_(float x) { return 1.f / (1.f + expf(-x)); }

// ---------------- lin0: out = relu(x @ lin0_W^T + b), also initial h -----
__global__ void k_lin0(const float* __restrict__ x, const float* __restrict__ W,
                       const float* __restrict__ b) {
    int idx = blockIdx.x * blockDim.x + threadIdx.x;
    if (idx >= NN * DD) return;
    int n = idx >> 6, o = idx & 63;
    const float* xr = x + n * 14;
    const float* wr = W + o * 14;
    float acc = b[o];
#pragma unroll
    for (int i = 0; i < 14; i++) acc += xr[i] * wr[i];
    g_out[idx] = fmaxf(acc, 0.f);
}

// ---------------- edge MLP layer 1: h1 = relu(ea @ e1_W^T + b) -----------
__global__ void k_edge1(const float* __restrict__ ea, const float* __restrict__ W,
                        const float* __restrict__ b) {
    int idx = blockIdx.x * blockDim.x + threadIdx.x;
    if (idx >= NE * 128) return;
    int e = idx >> 7, j = idx & 127;
    const float* er = ea + e * 4;
    const float* wr = W + j * 4;
    float acc = b[j];
#pragma unroll
    for (int i = 0; i < 4; i++) acc += er[i] * wr[i];
    g_h1[idx] = fmaxf(acc, 0.f);
}

// ---------------- W GEMM: g_W[E,4096] = g_h1[E,128] @ e2_W^T + e2_b ------
// 128x128 block tile, BK=8, 8x8 per thread, 256 threads.
__global__ __launch_bounds__(256) void k_wgemm(const float* __restrict__ e2W,
                                               const float* __restrict__ e2b) {
    __shared__ float As[8][132];
    __shared__ float Bs[8][132];
    int tid = threadIdx.x;
    int m0 = blockIdx.y * 128;
    int n0 = blockIdx.x * 128;
    int lrow = tid >> 1;
    int lk = (tid & 1) * 4;
    int tr = tid >> 4, tc = tid & 15;
    float acc[8][8];
#pragma unroll
    for (int i = 0; i < 8; i++)
#pragma unroll
        for (int j = 0; j < 8; j++) acc[i][j] = 0.f;

    for (int k0 = 0; k0 < 128; k0 += 8) {
        float4 av = *(const float4*)(g_h1 + (size_t)(m0 + lrow) * 128 + k0 + lk);
        float4 bv = *(const float4*)(e2W + (size_t)(n0 + lrow) * 128 + k0 + lk);
        As[lk + 0][lrow] = av.x; As[lk + 1][lrow] = av.y;
        As[lk + 2][lrow] = av.z; As[lk + 3][lrow] = av.w;
        Bs[lk + 0][lrow] = bv.x; Bs[lk + 1][lrow] = bv.y;
        Bs[lk + 2][lrow] = bv.z; Bs[lk + 3][lrow] = bv.w;
        __syncthreads();
#pragma unroll
        for (int k = 0; k < 8; k++) {
            float4 a0 = *(const float4*)&As[k][tr * 8];
            float4 a1 = *(const float4*)&As[k][tr * 8 + 4];
            float4 b0 = *(const float4*)&Bs[k][tc * 8];
            float4 b1 = *(const float4*)&Bs[k][tc * 8 + 4];
            float a[8] = {a0.x, a0.y, a0.z, a0.w, a1.x, a1.y, a1.z, a1.w};
            float bb[8] = {b0.x, b0.y, b0.z, b0.w, b1.x, b1.y, b1.z, b1.w};
#pragma unroll
            for (int i = 0; i < 8; i++)
#pragma unroll
                for (int j = 0; j < 8; j++) acc[i][j] += a[i] * bb[j];
        }
        __syncthreads();
    }
    int nb = n0 + tc * 8;
    float bia[8];
#pragma unroll
    for (int j = 0; j < 8; j++) bia[j] = e2b[nb + j];
#pragma unroll
    for (int i = 0; i < 8; i++) {
        int m = m0 + tr * 8 + i;
        float* wr = g_W + (size_t)m * 4096 + nb;
        float4 c0, c1;
        c0.x = acc[i][0] + bia[0]; c0.y = acc[i][1] + bia[1];
        c0.z = acc[i][2] + bia[2]; c0.w = acc[i][3] + bia[3];
        c1.x = acc[i][4] + bia[4]; c1.y = acc[i][5] + bia[5];
        c1.z = acc[i][6] + bia[6]; c1.w = acc[i][7] + bia[7];
        *(float4*)wr = c0;
        *(float4*)(wr + 4) = c1;
    }
}

// ---------------- init / counting ----------------------------------------
__global__ void k_zero_pre() {
    int i = blockIdx.x * blockDim.x + threadIdx.x;
    if (i < NN) g_cnt[i] = 0.f;
    if (i < NB) g_gcnt[i] = 0;
}
__global__ void k_cnt(const int* __restrict__ ei) {
    int e = blockIdx.x * blockDim.x + threadIdx.x;
    if (e < NE) atomicAdd(&g_cnt[ei[NE + e]], 1.f);
}
__global__ void k_gcnt(const int* __restrict__ batch) {
    int n = blockIdx.x * blockDim.x + threadIdx.x;
    if (n < NN) atomicAdd(&g_gcnt[batch[n]], 1);
}
__global__ void k_scan() {
    __shared__ int s[NB];
    int t = threadIdx.x;
    s[t] = g_gcnt[t];
    __syncthreads();
    for (int off = 1; off < NB; off <<= 1) {
        int v = (t >= off) ? s[t - off] : 0;
        __syncthreads();
        s[t] += v;
        __syncthreads();
    }
    g_gptr[t + 1] = s[t];
    if (t == 0) g_gptr[0] = 0;
}
__global__ void k_zero_agg() {
    int i = blockIdx.x * blockDim.x + threadIdx.x;
    if (i < NN * DD) g_agg[i] = 0.f;
}
__global__ void k_zero_s2s() {
    int i = blockIdx.x * blockDim.x + threadIdx.x;
    if (i < NB * 128) g_qstar[i] = 0.f;
    if (i < NB * 64) { g_hl[i] = 0.f; g_cl[i] = 0.f; }
}

// ---------------- messages: msg[e] = out[src] @ W[e]; scatter into agg ---
__global__ __launch_bounds__(256) void k_msg(const int* __restrict__ ei) {
    int le = threadIdx.x >> 6, t = threadIdx.x & 63;
    int e = blockIdx.x * 4 + le;
    __shared__ float s[4][64];
    int src = ei[e];
    int dst = ei[NE + e];
    s[le][t] = g_out[src * 64 + t];
    __syncthreads();
    const float* Wr = g_W + (size_t)e * 4096 + t;
    float acc = 0.f;
#pragma unroll
    for (int i = 0; i < 64; i++) acc += s[le][i] * Wr[i * 64];
    atomicAdd(&g_agg[dst * 64 + t], acc);
}

// ---------------- m = relu(agg/cnt + out@rootW + conv_b) -----------------
__global__ __launch_bounds__(256) void k_prem(const float* __restrict__ rootW,
                                              const float* __restrict__ convb) {
    __shared__ float sW[4096];
    int tid = threadIdx.x;
    for (int i = tid; i < 4096; i += 256) sW[i] = rootW[i];
    __syncthreads();
    int o = tid & 63, ln = tid >> 6;
    int base = blockIdx.x * 32;
    float cb = convb[o];
    for (int gg = 0; gg < 32; gg += 4) {
        int n = base + gg + ln;
        const float* orow = g_out + n * 64;
        float acc = 0.f;
#pragma unroll
        for (int i = 0; i < 64; i++) acc += orow[i] * sW[i * 64 + o];
        float c = g_cnt[n];
        if (c < 1.f) c = 1.f;
        float v = g_agg[n * 64 + o] / c + acc + cb;
        g_m[n * 64 + o] = fmaxf(v, 0.f);
    }
}

// ---------------- GRU cell over all nodes (16 nodes / block) -------------
__global__ __launch_bounds__(192) void k_gru(const float* __restrict__ Wih,
                                             const float* __restrict__ Whh,
                                             const float* __restrict__ bih,
                                             const float* __restrict__ bhh) {
    __shared__ float sm[16][64], sh[16][64], sgi[16][192], sgh[16][192];
    int tid = threadIdx.x;
    int base = blockIdx.x * 16;
    for (int i = tid; i < 1024; i += 192) {
        int n = i >> 6, c = i & 63;
        sm[n][c] = g_m[(base + n) * 64 + c];
        sh[n][c] = g_out[(base + n) * 64 + c];
    }
    __syncthreads();
    {
        float accI[16], accH[16];
#pragma unroll
        for (int j = 0; j < 16; j++) { accI[j] = 0.f; accH[j] = 0.f; }
        const float* wi = Wih + tid * 64;
        const float* wh = Whh + tid * 64;
        for (int i = 0; i < 64; i++) {
            float a = wi[i], b = wh[i];
#pragma unroll
            for (int j = 0; j < 16; j++) {
                accI[j] += sm[j][i] * a;
                accH[j] += sh[j][i] * b;
            }
        }
        float bi = bih[tid], bh = bhh[tid];
#pragma unroll
        for (int j = 0; j < 16; j++) {
            sgi[j][tid] = accI[j] + bi;
            sgh[j][tid] = accH[j] + bh;
        }
    }
    __syncthreads();
    for (int i = tid; i < 1024; i += 192) {
        int n = i >> 6, c = i & 63;
        float r = sigmoidf_(sgi[n][c] + sgh[n][c]);
        float z = sigmoidf_(sgi[n][64 + c] + sgh[n][64 + c]);
        float nn2 = tanhf(sgi[n][128 + c] + r * sgh[n][128 + c]);
        float hnew = (1.f - z) * nn2 + z * sh[n][c];
        g_out[(base + n) * 64 + c] = hnew;
    }
}

// ---------------- Set2Set LSTM cell (per graph) --------------------------
__global__ __launch_bounds__(256) void k_lstm(const float* __restrict__ Wih,
                                              const float* __restrict__ Whh,
                                              const float* __restrict__ bih,
                                              const float* __restrict__ bhh) {
    int g = blockIdx.x, j = threadIdx.x;
    __shared__ float sq[128], sh[64], sg[256];
    if (j < 128) sq[j] = g_qstar[g * 128 + j];
    else if (j < 192) sh[j - 128] = g_hl[g * 64 + j - 128];
    __syncthreads();
    float acc = bih[j] + bhh[j];
    const float* wi = Wih + j * 128;
#pragma unroll 8
    for (int k = 0; k < 128; k++) acc += sq[k] * wi[k];
    const float* wh = Whh + j * 64;
#pragma unroll 8
    for (int k = 0; k < 64; k++) acc += sh[k] * wh[k];
    sg[j] = acc;
    __syncthreads();
    if (j < 64) {
        float i_ = sg[j], f_ = sg[64 + j], gg = sg[128 + j], o_ = sg[192 + j];
        float c = sigmoidf_(f_) * g_cl[g * 64 + j] + sigmoidf_(i_) * tanhf(gg);
        float h = sigmoidf_(o_) * tanhf(c);
        g_cl[g * 64 + j] = c;
        g_hl[g * 64 + j] = h;
    }
}

// ---------------- Set2Set attention + readout (per graph, contiguous) ----
__global__ __launch_bounds__(64) void k_attn() {
    int g = blockIdx.x, t = threadIdx.x;
    int s = g_gptr[g], e2 = g_gptr[g + 1];
    __shared__ float sq[64], red[64];
    sq[t] = g_hl[g * 64 + t];
    __syncthreads();
    float mx = -3.0e38f;
    for (int n = s + t; n < e2; n += 64) {
        const float* orow = g_out + (size_t)n * 64;
        float acc = 0.f;
#pragma unroll
        for (int i = 0; i < 64; i++) acc += orow[i] * sq[i];
        g_e[n] = acc;
        mx = fmaxf(mx, acc);
    }
    red[t] = mx; __syncthreads();
    for (int st = 32; st > 0; st >>= 1) {
        if (t < st) red[t] = fmaxf(red[t], red[t + st]);
        __syncthreads();
    }
    mx = red[0]; __syncthreads();
    float den = 0.f;
    for (int n = s + t; n < e2; n += 64) {
        float ex = expf(g_e[n] - mx);
        g_e[n] = ex;
        den += ex;
    }
    red[t] = den; __syncthreads();
    for (int st = 32; st > 0; st >>= 1) {
        if (t < st) red[t] += red[t + st];
        __syncthreads();
    }
    den = red[0]; __syncthreads();
    float r = 0.f;
    for (int n = s; n < e2; n++) r += g_e[n] * g_out[(size_t)n * 64 + t];
    if (e2 > s) r /= den;
    g_qstar[g * 128 + t] = sq[t];
    g_qstar[g * 128 + 64 + t] = r;
}

// ---------------- final MLP head -----------------------------------------
__global__ __launch_bounds__(128) void k_final(const float* __restrict__ fc1W,
                                               const float* __restrict__ fc1b,
                                               const float* __restrict__ fc2W,
                                               const float* __restrict__ fc2b,
                                               float* __restrict__ outp) {
    int g = blockIdx.x, j = threadIdx.x;
    __shared__ float sq[128], red[128];
    sq[j] = g_qstar[g * 128 + j];
    __syncthreads();
    float acc = fc1b[j];
    const float* w = fc1W + j * 128;
#pragma unroll 8
    for (int k = 0; k < 128; k++) acc += sq[k] * w[k];
    red[j] = fmaxf(acc, 0.f) * fc2W[j];
    __syncthreads();
    for (int st = 64; st > 0; st >>= 1) {
        if (j < st) red[j] += red[j + st];
        __syncthreads();
    }
    if (j == 0) outp[g] = red[0] + fc2b[0];
}

// ---------------- host: launch sequence ----------------------------------
extern "C" void kernel_launch(void* const* d_in, const int* in_sizes, int n_in,
                              void* d_out, int out_size) {
    const float* x       = (const float*)d_in[0];
    const int*   ei      = (const int*)d_in[1];
    const float* ea      = (const float*)d_in[2];
    const int*   batch   = (const int*)d_in[3];
    const float* lin0_W  = (const float*)d_in[4];
    const float* lin0_b  = (const float*)d_in[5];
    const float* e1_W    = (const float*)d_in[6];
    const float* e1_b    = (const float*)d_in[7];
    const float* e2_W    = (const float*)d_in[8];
    const float* e2_b    = (const float*)d_in[9];
    const float* root_W  = (const float*)d_in[10];
    const float* conv_b  = (const float*)d_in[11];
    const float* gru_Wih = (const float*)d_in[12];
    const float* gru_Whh = (const float*)d_in[13];
    const float* gru_bih = (const float*)d_in[14];
    const float* gru_bhh = (const float*)d_in[15];
    const float* lstm_Wih = (const float*)d_in[16];
    const float* lstm_Whh = (const float*)d_in[17];
    const float* lstm_bih = (const float*)d_in[18];
    const float* lstm_bhh = (const float*)d_in[19];
    const float* fc1_W   = (const float*)d_in[20];
    const float* fc1_b   = (const float*)d_in[21];
    const float* fc2_W   = (const float*)d_in[22];
    const float* fc2_b   = (const float*)d_in[23];
    float* outp = (float*)d_out;

    k_lin0<<<(NN * DD) / 256, 256>>>(x, lin0_W, lin0_b);
    k_edge1<<<(NE * 128) / 256, 256>>>(ea, e1_W, e1_b);
    k_wgemm<<<dim3(4096 / 128, NE / 128), 256>>>(e2_W, e2_b);
    k_zero_pre<<<NN / 256, 256>>>();
    k_cnt<<<NE / 256, 256>>>(ei);
    k_gcnt<<<NN / 256, 256>>>(batch);
    k_scan<<<1, NB>>>();

    for (int it = 0; it < 3; it++) {
        k_zero_agg<<<(NN * DD) / 256, 256>>>();
        k_msg<<<NE / 4, 256>>>(ei);
        k_prem<<<NN / 32, 256>>>(root_W, conv_b);
        k_gru<<<NN / 16, 192>>>(gru_Wih, gru_Whh, gru_bih, gru_bhh);
    }

    k_zero_s2s<<<(NB * 128) / 256, 256>>>();
    for (int st = 0; st < 3; st++) {
        k_lstm<<<NB, 256>>>(lstm_Wih, lstm_Whh, lstm_bih, lstm_bhh);
        k_attn<<<NB, 64>>>();
    }
    k_final<<<NB, 128>>>(fc1_W, fc1_b, fc2_W, fc2_b, outp);
}

// round 4
// speedup vs baseline: 1.2289x; 1.2289x over previous
#include <cuda_runtime.h>
#include <cuda_bf16.h>
#include <math.h>
#include <cstdint>

#define NN 32768
#define NE 49152
#define NB 1024
#define DD 64

// ---------------- device scratch (no allocations allowed) ----------------
__device__ __nv_bfloat16 g_h1h[(size_t)NE * 128];   // edge MLP hidden, bf16 hi
__device__ __nv_bfloat16 g_h1l[(size_t)NE * 128];   // edge MLP hidden, bf16 lo
__device__ __nv_bfloat16 g_e2h[4096 * 128];         // e2_W hi
__device__ __nv_bfloat16 g_e2l[4096 * 128];         // e2_W lo
__device__ float g_W[(size_t)NE * 4096];            // edge weights (805 MB)
__device__ float g_out[NN * DD];                    // node features / GRU h
__device__ float g_m[NN * DD];                      // conv output m
__device__ float g_agg[NN * DD];                    // message accumulator
__device__ float g_cnt[NN];                         // in-degree (float)
__device__ int   g_gcnt[NB];                        // nodes per graph
__device__ int   g_gptr[NB + 1];                    // CSR over sorted batch
__device__ float g_qstar[NB * 2 * DD];
__device__ float g_hl[NB * DD];
__device__ float g_cl[NB * DD];
__device__ float g_e[NN];                           // attention logits / exp

__device__ __forceinline__ float sigmoidf_(float x) { return 1.f / (1.f + expf(-x)); }

__device__ __forceinline__ uint32_t smem_u32(const void* p) {
    uint32_t a;
    asm("{ .reg .u64 t; cvta.to.shared.u64 t, %1; cvt.u32.u64 %0, t; }" : "=r"(a) : "l"(p));
    return a;
}
__device__ __forceinline__ void ldsm_x4(uint32_t& r0, uint32_t& r1, uint32_t& r2, uint32_t& r3,
                                        uint32_t addr) {
    asm volatile("ldmatrix.sync.aligned.m8n8.x4.shared.b16 {%0, %1, %2, %3}, [%4];"
                 : "=r"(r0), "=r"(r1), "=r"(r2), "=r"(r3) : "r"(addr));
}
__device__ __forceinline__ void mma16816(float* d, const uint32_t* a, const uint32_t* b) {
    asm volatile(
        "mma.sync.aligned.m16n8k16.row.col.f32.bf16.bf16.f32 "
        "{%0, %1, %2, %3}, {%4, %5, %6, %7}, {%8, %9}, {%0, %1, %2, %3};"
        : "+f"(d[0]), "+f"(d[1]), "+f"(d[2]), "+f"(d[3])
        : "r"(a[0]), "r"(a[1]), "r"(a[2]), "r"(a[3]), "r"(b[0]), "r"(b[1]));
}

// copy a [128 rows x 128 bf16] K-major tile into smem with 16B-chunk XOR swizzle:
// byte(row, chunk) = row*256 + ((chunk ^ (row & 7)) * 16)
__device__ __forceinline__ void copy_sw(char* dst, const __nv_bfloat16* __restrict__ src) {
    int tid = threadIdx.x;
#pragma unroll
    for (int it = 0; it < 8; it++) {
        int i = tid + it * 256;          // 2048 16B-chunks
        int row = i >> 4;
        int chunk = i & 15;
        uint4 v = *(const uint4*)(src + (size_t)row * 128 + chunk * 8);
        *(uint4*)(dst + row * 256 + ((chunk ^ (row & 7)) << 4)) = v;
    }
}

// ============ W GEMM (HMMA): g_W[E,4096] = h1 @ e2W^T + b =================
// Split-bf16 3-pass: AhBh + AhBl + AlBh, fp32 register accumulators.
// CTA: 128 edges x full 4096 N in 32 stripes of 128. 8 warps: 2(M) x 4(N),
// warp tile 64x32. B stripes (e2 split, 2 MB total) stay L2-resident.
__global__ __launch_bounds__(256) void k_wgemm_tc(const float* __restrict__ e2b) {
    extern __shared__ char dyn[];
    char* pAh = dyn;                 // 32 KB
    char* pAl = dyn + 32768;
    char* pBh = dyn + 65536;
    char* pBl = dyn + 98304;

    int tid = threadIdx.x, wid = tid >> 5, lane = tid & 31;
    int m0 = blockIdx.x * 128;
    int wm = wid & 1;                // warp M: 0..1 (64 rows each)
    int wn = wid >> 1;               // warp N: 0..3 (32 cols each)

    copy_sw(pAh, g_h1h + (size_t)m0 * 128);
    copy_sw(pAl, g_h1l + (size_t)m0 * 128);

    // precompute per-lane ldmatrix base addresses (row part)
    int lrow = lane & 7;             // row within 8x8 matrix
    int lsel = lane >> 3;            // which of the 4 matrices
    // A: matrices 0,1 = rows base,base+8 (chunk c); 2,3 = same rows (chunk c+1)
    int a_row_off = (lsel & 1) * 8 + lrow;          // 0/8 + lrow
    int a_chunk_sel = lsel >> 1;                    // 0 or 1
    // B: matrices 0,1 = rows base (chunk c, c+1); 2,3 = rows base+8 (chunk c, c+1)
    int b_row_off = (lsel >> 1) * 8 + lrow;
    int b_chunk_sel = lsel & 1;

    uint32_t uAh = smem_u32(pAh), uAl = smem_u32(pAl);
    uint32_t uBh = smem_u32(pBh), uBl = smem_u32(pBl);

    for (int s = 0; s < 32; s++) {
        __syncthreads();             // previous stripe fully consumed
        copy_sw(pBh, g_e2h + (size_t)s * 128 * 128);
        copy_sw(pBl, g_e2l + (size_t)s * 128 * 128);
        __syncthreads();

        float acc[4][4][4];          // [mtile][ntile][frag]
#pragma unroll
        for (int i = 0; i < 4; i++)
#pragma unroll
            for (int j = 0; j < 4; j++)
#pragma unroll
                for (int q = 0; q < 4; q++) acc[i][j][q] = 0.f;

#pragma unroll
        for (int p = 0; p < 3; p++) {
            uint32_t uA = (p == 2) ? uAl : uAh;
            uint32_t uB = (p == 1) ? uBl : uBh;
#pragma unroll
            for (int ks = 0; ks < 8; ks++) {
                int c0 = ks * 2;
                uint32_t afr[4][4];
#pragma unroll
                for (int mt = 0; mt < 4; mt++) {
                    int row = wm * 64 + mt * 16 + a_row_off;
                    int ch = c0 + a_chunk_sel;
                    uint32_t addr = uA + row * 256 + (((ch ^ (row & 7)) & 15) << 4);
                    ldsm_x4(afr[mt][0], afr[mt][1], afr[mt][2], afr[mt][3], addr);
                }
                uint32_t bfr[2][4];
#pragma unroll
                for (int bt = 0; bt < 2; bt++) {
                    int row = wn * 32 + bt * 16 + b_row_off;
                    int ch = c0 + b_chunk_sel;
                    uint32_t addr = uB + row * 256 + (((ch ^ (row & 7)) & 15) << 4);
                    ldsm_x4(bfr[bt][0], bfr[bt][1], bfr[bt][2], bfr[bt][3], addr);
                }
#pragma unroll
                for (int mt = 0; mt < 4; mt++)
#pragma unroll
                    for (int nt = 0; nt < 4; nt++)
                        mma16816(acc[mt][nt], afr[mt], bfr[nt >> 1] + (nt & 1) * 2);
            }
        }

        // epilogue: D[m][n] frag layout: c0,c1 -> (row g, cols t*2,t*2+1); c2,c3 -> row g+8
        int g = lane >> 2, t4 = lane & 3;
        int n0 = s * 128 + wn * 32;
#pragma unroll
        for (int mt = 0; mt < 4; mt++) {
            int mrow = m0 + wm * 64 + mt * 16 + g;
#pragma unroll
            for (int nt = 0; nt < 4; nt++) {
                int col = n0 + nt * 8 + t4 * 2;
                float b0 = e2b[col], b1 = e2b[col + 1];
                float* d0 = g_W + (size_t)mrow * 4096 + col;
                float* d1 = g_W + (size_t)(mrow + 8) * 4096 + col;
                float2 v0 = make_float2(acc[mt][nt][0] + b0, acc[mt][nt][1] + b1);
                float2 v1 = make_float2(acc[mt][nt][2] + b0, acc[mt][nt][3] + b1);
                *(float2*)d0 = v0;
                *(float2*)d1 = v1;
            }
        }
    }
}

// ---------------- lin0: out = relu(x @ lin0_W^T + b) ----------------------
__global__ void k_lin0(const float* __restrict__ x, const float* __restrict__ W,
                       const float* __restrict__ b) {
    int idx = blockIdx.x * blockDim.x + threadIdx.x;
    if (idx >= NN * DD) return;
    int n = idx >> 6, o = idx & 63;
    const float* xr = x + n * 14;
    const float* wr = W + o * 14;
    float acc = b[o];
#pragma unroll
    for (int i = 0; i < 14; i++) acc += xr[i] * wr[i];
    g_out[idx] = fmaxf(acc, 0.f);
}

// ---- edge MLP layer 1: h1 = relu(ea @ e1_W^T + b), write split bf16 ------
__global__ void k_edge1(const float* __restrict__ ea, const float* __restrict__ W,
                        const float* __restrict__ b) {
    int idx = blockIdx.x * blockDim.x + threadIdx.x;
    if (idx >= NE * 128) return;
    int e = idx >> 7, j = idx & 127;
    const float* er = ea + e * 4;
    const float* wr = W + j * 4;
    float acc = b[j];
#pragma unroll
    for (int i = 0; i < 4; i++) acc += er[i] * wr[i];
    acc = fmaxf(acc, 0.f);
    __nv_bfloat16 hi = __float2bfloat16(acc);
    g_h1h[idx] = hi;
    g_h1l[idx] = __float2bfloat16(acc - __bfloat162float(hi));
}

// ---------------- split e2_W into hi/lo bf16 ------------------------------
__global__ void k_e2split(const float* __restrict__ e2W) {
    int idx = blockIdx.x * blockDim.x + threadIdx.x;
    if (idx >= 4096 * 128) return;
    float v = e2W[idx];
    __nv_bfloat16 hi = __float2bfloat16(v);
    g_e2h[idx] = hi;
    g_e2l[idx] = __float2bfloat16(v - __bfloat162float(hi));
}

// ---------------- init / counting ----------------------------------------
__global__ void k_zero_pre() {
    int i = blockIdx.x * blockDim.x + threadIdx.x;
    if (i < NN) g_cnt[i] = 0.f;
    if (i < NB) g_gcnt[i] = 0;
}
__global__ void k_cnt(const int* __restrict__ ei) {
    int e = blockIdx.x * blockDim.x + threadIdx.x;
    if (e < NE) atomicAdd(&g_cnt[ei[NE + e]], 1.f);
}
__global__ void k_gcnt(const int* __restrict__ batch) {
    int n = blockIdx.x * blockDim.x + threadIdx.x;
    if (n < NN) atomicAdd(&g_gcnt[batch[n]], 1);
}
__global__ void k_scan() {
    __shared__ int s[NB];
    int t = threadIdx.x;
    s[t] = g_gcnt[t];
    __syncthreads();
    for (int off = 1; off < NB; off <<= 1) {
        int v = (t >= off) ? s[t - off] : 0;
        __syncthreads();
        s[t] += v;
        __syncthreads();
    }
    g_gptr[t + 1] = s[t];
    if (t == 0) g_gptr[0] = 0;
}
__global__ void k_zero_agg() {
    int i = blockIdx.x * blockDim.x + threadIdx.x;
    if (i < NN * DD) g_agg[i] = 0.f;
}
__global__ void k_zero_s2s() {
    int i = blockIdx.x * blockDim.x + threadIdx.x;
    if (i < NB * 128) g_qstar[i] = 0.f;
    if (i < NB * 64) { g_hl[i] = 0.f; g_cl[i] = 0.f; }
}

// ---------------- messages: msg[e] = out[src] @ W[e]; scatter into agg ---
__global__ __launch_bounds__(256) void k_msg(const int* __restrict__ ei) {
    int le = threadIdx.x >> 6, t = threadIdx.x & 63;
    int e = blockIdx.x * 4 + le;
    __shared__ float s[4][64];
    int src = ei[e];
    int dst = ei[NE + e];
    s[le][t] = g_out[src * 64 + t];
    __syncthreads();
    const float* Wr = g_W + (size_t)e * 4096 + t;
    float acc = 0.f;
#pragma unroll
    for (int i = 0; i < 64; i++) acc += s[le][i] * Wr[i * 64];
    atomicAdd(&g_agg[dst * 64 + t], acc);
}

// ---------------- m = relu(agg/cnt + out@rootW + conv_b) -----------------
__global__ __launch_bounds__(256) void k_prem(const float* __restrict__ rootW,
                                              const float* __restrict__ convb) {
    __shared__ float sW[4096];
    int tid = threadIdx.x;
    for (int i = tid; i < 4096; i += 256) sW[i] = rootW[i];
    __syncthreads();
    int o = tid & 63, ln = tid >> 6;
    int base = blockIdx.x * 32;
    float cb = convb[o];
    for (int gg = 0; gg < 32; gg += 4) {
        int n = base + gg + ln;
        const float* orow = g_out + n * 64;
        float acc = 0.f;
#pragma unroll
        for (int i = 0; i < 64; i++) acc += orow[i] * sW[i * 64 + o];
        float c = g_cnt[n];
        if (c < 1.f) c = 1.f;
        float v = g_agg[n * 64 + o] / c + acc + cb;
        g_m[n * 64 + o] = fmaxf(v, 0.f);
    }
}

// ---------------- GRU cell over all nodes (16 nodes / block) -------------
__global__ __launch_bounds__(192) void k_gru(const float* __restrict__ Wih,
                                             const float* __restrict__ Whh,
                                             const float* __restrict__ bih,
                                             const float* __restrict__ bhh) {
    __shared__ float sm[16][64], sh[16][64], sgi[16][192], sgh[16][192];
    int tid = threadIdx.x;
    int base = blockIdx.x * 16;
    for (int i = tid; i < 1024; i += 192) {
        int n = i >> 6, c = i & 63;
        sm[n][c] = g_m[(base + n) * 64 + c];
        sh[n][c] = g_out[(base + n) * 64 + c];
    }
    __syncthreads();
    {
        float accI[16], accH[16];
#pragma unroll
        for (int j = 0; j < 16; j++) { accI[j] = 0.f; accH[j] = 0.f; }
        const float* wi = Wih + tid * 64;
        const float* wh = Whh + tid * 64;
        for (int i = 0; i < 64; i++) {
            float a = wi[i], b = wh[i];
#pragma unroll
            for (int j = 0; j < 16; j++) {
                accI[j] += sm[j][i] * a;
                accH[j] += sh[j][i] * b;
            }
        }
        float bi = bih[tid], bh = bhh[tid];
#pragma unroll
        for (int j = 0; j < 16; j++) {
            sgi[j][tid] = accI[j] + bi;
            sgh[j][tid] = accH[j] + bh;
        }
    }
    __syncthreads();
    for (int i = tid; i < 1024; i += 192) {
        int n = i >> 6, c = i & 63;
        float r = sigmoidf_(sgi[n][c] + sgh[n][c]);
        float z = sigmoidf_(sgi[n][64 + c] + sgh[n][64 + c]);
        float nn2 = tanhf(sgi[n][128 + c] + r * sgh[n][128 + c]);
        float hnew = (1.f - z) * nn2 + z * sh[n][c];
        g_out[(base + n) * 64 + c] = hnew;
    }
}

// ---------------- Set2Set LSTM cell (per graph) --------------------------
__global__ __launch_bounds__(256) void k_lstm(const float* __restrict__ Wih,
                                              const float* __restrict__ Whh,
                                              const float* __restrict__ bih,
                                              const float* __restrict__ bhh) {
    int g = blockIdx.x, j = threadIdx.x;
    __shared__ float sq[128], sh[64], sg[256];
    if (j < 128) sq[j] = g_qstar[g * 128 + j];
    else if (j < 192) sh[j - 128] = g_hl[g * 64 + j - 128];
    __syncthreads();
    float acc = bih[j] + bhh[j];
    const float* wi = Wih + j * 128;
#pragma unroll 8
    for (int k = 0; k < 128; k++) acc += sq[k] * wi[k];
    const float* wh = Whh + j * 64;
#pragma unroll 8
    for (int k = 0; k < 64; k++) acc += sh[k] * wh[k];
    sg[j] = acc;
    __syncthreads();
    if (j < 64) {
        float i_ = sg[j], f_ = sg[64 + j], gg = sg[128 + j], o_ = sg[192 + j];
        float c = sigmoidf_(f_) * g_cl[g * 64 + j] + sigmoidf_(i_) * tanhf(gg);
        float h = sigmoidf_(o_) * tanhf(c);
        g_cl[g * 64 + j] = c;
        g_hl[g * 64 + j] = h;
    }
}

// ---------------- Set2Set attention + readout (per graph, contiguous) ----
__global__ __launch_bounds__(64) void k_attn() {
    int g = blockIdx.x, t = threadIdx.x;
    int s = g_gptr[g], e2 = g_gptr[g + 1];
    __shared__ float sq[64], red[64];
    sq[t] = g_hl[g * 64 + t];
    __syncthreads();
    float mx = -3.0e38f;
    for (int n = s + t; n < e2; n += 64) {
        const float* orow = g_out + (size_t)n * 64;
        float acc = 0.f;
#pragma unroll
        for (int i = 0; i < 64; i++) acc += orow[i] * sq[i];
        g_e[n] = acc;
        mx = fmaxf(mx, acc);
    }
    red[t] = mx; __syncthreads();
    for (int st = 32; st > 0; st >>= 1) {
        if (t < st) red[t] = fmaxf(red[t], red[t + st]);
        __syncthreads();
    }
    mx = red[0]; __syncthreads();
    float den = 0.f;
    for (int n = s + t; n < e2; n += 64) {
        float ex = expf(g_e[n] - mx);
        g_e[n] = ex;
        den += ex;
    }
    red[t] = den; __syncthreads();
    for (int st = 32; st > 0; st >>= 1) {
        if (t < st) red[t] += red[t + st];
        __syncthreads();
    }
    den = red[0]; __syncthreads();
    float r = 0.f;
    for (int n = s; n < e2; n++) r += g_e[n] * g_out[(size_t)n * 64 + t];
    if (e2 > s) r /= den;
    g_qstar[g * 128 + t] = sq[t];
    g_qstar[g * 128 + 64 + t] = r;
}

// ---------------- final MLP head -----------------------------------------
__global__ __launch_bounds__(128) void k_final(const float* __restrict__ fc1W,
                                               const float* __restrict__ fc1b,
                                               const float* __restrict__ fc2W,
                                               const float* __restrict__ fc2b,
                                               float* __restrict__ outp) {
    int g = blockIdx.x, j = threadIdx.x;
    __shared__ float sq[128], red[128];
    sq[j] = g_qstar[g * 128 + j];
    __syncthreads();
    float acc = fc1b[j];
    const float* w = fc1W + j * 128;
#pragma unroll 8
    for (int k = 0; k < 128; k++) acc += sq[k] * w[k];
    red[j] = fmaxf(acc, 0.f) * fc2W[j];
    __syncthreads();
    for (int st = 64; st > 0; st >>= 1) {
        if (j < st) red[j] += red[j + st];
        __syncthreads();
    }
    if (j == 0) outp[g] = red[0] + fc2b[0];
}

// ---------------- host: launch sequence ----------------------------------
extern "C" void kernel_launch(void* const* d_in, const int* in_sizes, int n_in,
                              void* d_out, int out_size) {
    const float* x       = (const float*)d_in[0];
    const int*   ei      = (const int*)d_in[1];
    const float* ea      = (const float*)d_in[2];
    const int*   batch   = (const int*)d_in[3];
    const float* lin0_W  = (const float*)d_in[4];
    const float* lin0_b  = (const float*)d_in[5];
    const float* e1_W    = (const float*)d_in[6];
    const float* e1_b    = (const float*)d_in[7];
    const float* e2_W    = (const float*)d_in[8];
    const float* e2_b    = (const float*)d_in[9];
    const float* root_W  = (const float*)d_in[10];
    const float* conv_b  = (const float*)d_in[11];
    const float* gru_Wih = (const float*)d_in[12];
    const float* gru_Whh = (const float*)d_in[13];
    const float* gru_bih = (const float*)d_in[14];
    const float* gru_bhh = (const float*)d_in[15];
    const float* lstm_Wih = (const float*)d_in[16];
    const float* lstm_Whh = (const float*)d_in[17];
    const float* lstm_bih = (const float*)d_in[18];
    const float* lstm_bhh = (const float*)d_in[19];
    const float* fc1_W   = (const float*)d_in[20];
    const float* fc1_b   = (const float*)d_in[21];
    const float* fc2_W   = (const float*)d_in[22];
    const float* fc2_b   = (const float*)d_in[23];
    float* outp = (float*)d_out;

    static bool attr_set = false;
    const int WG_SMEM = 4 * 32768;
    if (!attr_set) {
        cudaFuncSetAttribute(k_wgemm_tc, cudaFuncAttributeMaxDynamicSharedMemorySize, WG_SMEM);
        attr_set = true;
    }

    // launches 1-5, then k_wgemm_tc as the 6th launch (ncu -s 5 -c 1 captures it)
    k_lin0<<<(NN * DD) / 256, 256>>>(x, lin0_W, lin0_b);
    k_edge1<<<(NE * 128) / 256, 256>>>(ea, e1_W, e1_b);
    k_e2split<<<(4096 * 128) / 256, 256>>>(e2_W);
    k_zero_pre<<<NN / 256, 256>>>();
    k_gcnt<<<NN / 256, 256>>>(batch);
    k_wgemm_tc<<<NE / 128, 256, WG_SMEM>>>(e2_b);
    k_cnt<<<NE / 256, 256>>>(ei);
    k_scan<<<1, NB>>>();

    for (int it = 0; it < 3; it++) {
        k_zero_agg<<<(NN * DD) / 256, 256>>>();
        k_msg<<<NE / 4, 256>>>(ei);
        k_prem<<<NN / 32, 256>>>(root_W, conv_b);
        k_gru<<<NN / 16, 192>>>(gru_Wih, gru_Whh, gru_bih, gru_bhh);
    }

    k_zero_s2s<<<(NB * 128) / 256, 256>>>();
    for (int st = 0; st < 3; st++) {
        k_lstm<<<NB, 256>>>(lstm_Wih, lstm_Whh, lstm_bih, lstm_bhh);
        k_attn<<<NB, 64>>>();
    }
    k_final<<<NB, 128>>>(fc1_W, fc1_b, fc2_W, fc2_b, outp);
}

// round 5
// speedup vs baseline: 1.3042x; 1.0612x over previous
#include <cuda_runtime.h>
#include <cuda_bf16.h>
#include <math.h>
#include <cstdint>

#define NN 32768
#define NE 49152
#define NB 1024
#define DD 64

// ---------------- device scratch (no allocations allowed) ----------------
__device__ __nv_bfloat16 g_h1h[(size_t)NE * 128];   // edge MLP hidden, bf16 hi
__device__ __nv_bfloat16 g_h1l[(size_t)NE * 128];   // edge MLP hidden, bf16 lo
__device__ __nv_bfloat16 g_e2h[4096 * 128];         // e2_W hi
__device__ __nv_bfloat16 g_e2l[4096 * 128];         // e2_W lo
__device__ __nv_bfloat16 g_Wb[(size_t)NE * 4096];   // edge weights (bf16, 402 MB)
__device__ float g_out[NN * DD];                    // node features / GRU h
__device__ float g_m[NN * DD];                      // conv output m
__device__ float g_agg[NN * DD];                    // message accumulator
__device__ float g_cnt[NN];                         // in-degree (float)
__device__ int   g_gcnt[NB];                        // nodes per graph
__device__ int   g_gptr[NB + 1];                    // CSR over sorted batch
__device__ float g_qstar[NB * 2 * DD];
__device__ float g_hl[NB * DD];
__device__ float g_cl[NB * DD];
__device__ float g_e[NN];                           // attention logits / exp

__device__ __forceinline__ float sigmoidf_(float x) { return 1.f / (1.f + expf(-x)); }

__device__ __forceinline__ uint32_t smem_u32(const void* p) {
    uint32_t a;
    asm("{ .reg .u64 t; cvta.to.shared.u64 t, %1; cvt.u32.u64 %0, t; }" : "=r"(a) : "l"(p));
    return a;
}
__device__ __forceinline__ void ldsm_x4(uint32_t& r0, uint32_t& r1, uint32_t& r2, uint32_t& r3,
                                        uint32_t addr) {
    asm volatile("ldmatrix.sync.aligned.m8n8.x4.shared.b16 {%0, %1, %2, %3}, [%4];"
                 : "=r"(r0), "=r"(r1), "=r"(r2), "=r"(r3) : "r"(addr));
}
__device__ __forceinline__ void mma16816(float* d, const uint32_t* a, const uint32_t* b) {
    asm volatile(
        "mma.sync.aligned.m16n8k16.row.col.f32.bf16.bf16.f32 "
        "{%0, %1, %2, %3}, {%4, %5, %6, %7}, {%8, %9}, {%0, %1, %2, %3};"
        : "+f"(d[0]), "+f"(d[1]), "+f"(d[2]), "+f"(d[3])
        : "r"(a[0]), "r"(a[1]), "r"(a[2]), "r"(a[3]), "r"(b[0]), "r"(b[1]));
}

// copy a [128 rows x 128 bf16] K-major tile into smem with 16B-chunk XOR swizzle:
// byte(row, chunk) = row*256 + ((chunk ^ (row & 7)) * 16)
__device__ __forceinline__ void copy_sw(char* dst, const __nv_bfloat16* __restrict__ src) {
    int tid = threadIdx.x;
#pragma unroll
    for (int it = 0; it < 8; it++) {
        int i = tid + it * 256;          // 2048 16B-chunks
        int row = i >> 4;
        int chunk = i & 15;
        uint4 v = *(const uint4*)(src + (size_t)row * 128 + chunk * 8);
        *(uint4*)(dst + row * 256 + ((chunk ^ (row & 7)) << 4)) = v;
    }
}

// ============ W GEMM (HMMA): g_Wb[E,4096] = bf16(h1 @ e2W^T + b) ==========
// Split-bf16 3-pass: AhBh + AhBl + AlBh, fp32 register accumulators.
// CTA: 128 edges x 4096 N in 32 stripes of 128. 8 warps: 2(M) x 4(N).
// Epilogue staged through padded smem for fully-coalesced bf16 writes.
#define STG_STRIDE 272
__global__ __launch_bounds__(256) void k_wgemm_tc(const float* __restrict__ e2b) {
    extern __shared__ char dyn[];
    char* pAh = dyn;                 // 32 KB each
    char* pAl = dyn + 32768;
    char* pBh = dyn + 65536;
    char* pBl = dyn + 98304;
    char* pStage = dyn + 131072;     // 128 x 272 B = 34816 B

    int tid = threadIdx.x, wid = tid >> 5, lane = tid & 31;
    int m0 = blockIdx.x * 128;
    int wm = wid & 1;                // warp M: 0..1 (64 rows each)
    int wn = wid >> 1;               // warp N: 0..3 (32 cols each)

    copy_sw(pAh, g_h1h + (size_t)m0 * 128);
    copy_sw(pAl, g_h1l + (size_t)m0 * 128);

    int lrow = lane & 7;
    int lsel = lane >> 3;
    int a_row_off = (lsel & 1) * 8 + lrow;
    int a_chunk_sel = lsel >> 1;
    int b_row_off = (lsel >> 1) * 8 + lrow;
    int b_chunk_sel = lsel & 1;

    uint32_t uAh = smem_u32(pAh), uAl = smem_u32(pAl);
    uint32_t uBh = smem_u32(pBh), uBl = smem_u32(pBl);
    int g = lane >> 2, t4 = lane & 3;

    for (int s = 0; s < 32; s++) {
        copy_sw(pBh, g_e2h + (size_t)s * 128 * 128);
        copy_sw(pBl, g_e2l + (size_t)s * 128 * 128);
        __syncthreads();

        float acc[4][4][4];
#pragma unroll
        for (int i = 0; i < 4; i++)
#pragma unroll
            for (int j = 0; j < 4; j++)
#pragma unroll
                for (int q = 0; q < 4; q++) acc[i][j][q] = 0.f;

#pragma unroll
        for (int p = 0; p < 3; p++) {
            uint32_t uA = (p == 2) ? uAl : uAh;
            uint32_t uB = (p == 1) ? uBl : uBh;
#pragma unroll
            for (int ks = 0; ks < 8; ks++) {
                int c0 = ks * 2;
                uint32_t afr[4][4];
#pragma unroll
                for (int mt = 0; mt < 4; mt++) {
                    int row = wm * 64 + mt * 16 + a_row_off;
                    int ch = c0 + a_chunk_sel;
                    uint32_t addr = uA + row * 256 + (((ch ^ (row & 7)) & 15) << 4);
                    ldsm_x4(afr[mt][0], afr[mt][1], afr[mt][2], afr[mt][3], addr);
                }
                uint32_t bfr[2][4];
#pragma unroll
                for (int bt = 0; bt < 2; bt++) {
                    int row = wn * 32 + bt * 16 + b_row_off;
                    int ch = c0 + b_chunk_sel;
                    uint32_t addr = uB + row * 256 + (((ch ^ (row & 7)) & 15) << 4);
                    ldsm_x4(bfr[bt][0], bfr[bt][1], bfr[bt][2], bfr[bt][3], addr);
                }
#pragma unroll
                for (int mt = 0; mt < 4; mt++)
#pragma unroll
                    for (int nt = 0; nt < 4; nt++)
                        mma16816(acc[mt][nt], afr[mt], bfr[nt >> 1] + (nt & 1) * 2);
            }
        }

        // ---- staged epilogue: fp32 + bias -> bf16 -> smem -> coalesced GMEM ----
#pragma unroll
        for (int mt = 0; mt < 4; mt++) {
            int r0 = wm * 64 + mt * 16 + g;
#pragma unroll
            for (int nt = 0; nt < 4; nt++) {
                int col = wn * 32 + nt * 8 + t4 * 2;
                float b0 = e2b[s * 128 + col], b1 = e2b[s * 128 + col + 1];
                __nv_bfloat162 v0 = __floats2bfloat162_rn(acc[mt][nt][0] + b0, acc[mt][nt][1] + b1);
                __nv_bfloat162 v1 = __floats2bfloat162_rn(acc[mt][nt][2] + b0, acc[mt][nt][3] + b1);
                *(__nv_bfloat162*)(pStage + r0 * STG_STRIDE + col * 2) = v0;
                *(__nv_bfloat162*)(pStage + (r0 + 8) * STG_STRIDE + col * 2) = v1;
            }
        }
        __syncthreads();
#pragma unroll
        for (int it = 0; it < 8; it++) {
            int i = tid + it * 256;
            int row = i >> 4, ch = i & 15;
            uint4 v = *(const uint4*)(pStage + row * STG_STRIDE + ch * 16);
            *(uint4*)((char*)(g_Wb + (size_t)(m0 + row) * 4096 + s * 128) + ch * 16) = v;
        }
        __syncthreads();
    }
}

// ---------------- lin0: out = relu(x @ lin0_W^T + b) ----------------------
__global__ void k_lin0(const float* __restrict__ x, const float* __restrict__ W,
                       const float* __restrict__ b) {
    int idx = blockIdx.x * blockDim.x + threadIdx.x;
    if (idx >= NN * DD) return;
    int n = idx >> 6, o = idx & 63;
    const float* xr = x + n * 14;
    const float* wr = W + o * 14;
    float acc = b[o];
#pragma unroll
    for (int i = 0; i < 14; i++) acc += xr[i] * wr[i];
    g_out[idx] = fmaxf(acc, 0.f);
}

// ---- edge MLP layer 1: h1 = relu(ea @ e1_W^T + b), write split bf16 ------
__global__ void k_edge1(const float* __restrict__ ea, const float* __restrict__ W,
                        const float* __restrict__ b) {
    int idx = blockIdx.x * blockDim.x + threadIdx.x;
    if (idx >= NE * 128) return;
    int e = idx >> 7, j = idx & 127;
    const float* er = ea + e * 4;
    const float* wr = W + j * 4;
    float acc = b[j];
#pragma unroll
    for (int i = 0; i < 4; i++) acc += er[i] * wr[i];
    acc = fmaxf(acc, 0.f);
    __nv_bfloat16 hi = __float2bfloat16(acc);
    g_h1h[idx] = hi;
    g_h1l[idx] = __float2bfloat16(acc - __bfloat162float(hi));
}

// ---------------- split e2_W into hi/lo bf16 ------------------------------
__global__ void k_e2split(const float* __restrict__ e2W) {
    int idx = blockIdx.x * blockDim.x + threadIdx.x;
    if (idx >= 4096 * 128) return;
    float v = e2W[idx];
    __nv_bfloat16 hi = __float2bfloat16(v);
    g_e2h[idx] = hi;
    g_e2l[idx] = __float2bfloat16(v - __bfloat162float(hi));
}

// ---------------- init / counting ----------------------------------------
__global__ void k_zero_pre() {
    int i = blockIdx.x * blockDim.x + threadIdx.x;
    if (i < NN) g_cnt[i] = 0.f;
    if (i < NB) g_gcnt[i] = 0;
}
__global__ void k_cnt(const int* __restrict__ ei) {
    int e = blockIdx.x * blockDim.x + threadIdx.x;
    if (e < NE) atomicAdd(&g_cnt[ei[NE + e]], 1.f);
}
__global__ void k_gcnt(const int* __restrict__ batch) {
    int n = blockIdx.x * blockDim.x + threadIdx.x;
    if (n < NN) atomicAdd(&g_gcnt[batch[n]], 1);
}
__global__ void k_scan() {
    __shared__ int s[NB];
    int t = threadIdx.x;
    s[t] = g_gcnt[t];
    __syncthreads();
    for (int off = 1; off < NB; off <<= 1) {
        int v = (t >= off) ? s[t - off] : 0;
        __syncthreads();
        s[t] += v;
        __syncthreads();
    }
    g_gptr[t + 1] = s[t];
    if (t == 0) g_gptr[0] = 0;
}
__global__ void k_zero_agg() {
    int i = blockIdx.x * blockDim.x + threadIdx.x;
    if (i < NN * DD) g_agg[i] = 0.f;
}
__global__ void k_zero_s2s() {
    int i = blockIdx.x * blockDim.x + threadIdx.x;
    if (i < NB * 128) g_qstar[i] = 0.f;
    if (i < NB * 64) { g_hl[i] = 0.f; g_cl[i] = 0.f; }
}

// ---------------- messages: msg[e] = out[src] @ W[e]; scatter into agg ---
__global__ __launch_bounds__(256) void k_msg(const int* __restrict__ ei) {
    int le = threadIdx.x >> 6, t = threadIdx.x & 63;
    int e = blockIdx.x * 4 + le;
    __shared__ float s[4][64];
    int src = ei[e];
    int dst = ei[NE + e];
    s[le][t] = g_out[src * 64 + t];
    __syncthreads();
    const __nv_bfloat16* Wr = g_Wb + (size_t)e * 4096 + t;
    float acc = 0.f;
#pragma unroll
    for (int i = 0; i < 64; i++) acc += s[le][i] * __bfloat162float(Wr[i * 64]);
    atomicAdd(&g_agg[dst * 64 + t], acc);
}

// ---------------- m = relu(agg/cnt + out@rootW + conv_b) -----------------
__global__ __launch_bounds__(256) void k_prem(const float* __restrict__ rootW,
                                              const float* __restrict__ convb) {
    __shared__ float sW[4096];
    int tid = threadIdx.x;
    for (int i = tid; i < 4096; i += 256) sW[i] = rootW[i];
    __syncthreads();
    int o = tid & 63, ln = tid >> 6;
    int base = blockIdx.x * 32;
    float cb = convb[o];
    for (int gg = 0; gg < 32; gg += 4) {
        int n = base + gg + ln;
        const float* orow = g_out + n * 64;
        float acc = 0.f;
#pragma unroll
        for (int i = 0; i < 64; i++) acc += orow[i] * sW[i * 64 + o];
        float c = g_cnt[n];
        if (c < 1.f) c = 1.f;
        float v = g_agg[n * 64 + o] / c + acc + cb;
        g_m[n * 64 + o] = fmaxf(v, 0.f);
    }
}

// ---------------- GRU cell over all nodes (16 nodes / block) -------------
__global__ __launch_bounds__(192) void k_gru(const float* __restrict__ Wih,
                                             const float* __restrict__ Whh,
                                             const float* __restrict__ bih,
                                             const float* __restrict__ bhh) {
    __shared__ float sm[16][64], sh[16][64], sgi[16][192], sgh[16][192];
    int tid = threadIdx.x;
    int base = blockIdx.x * 16;
    for (int i = tid; i < 1024; i += 192) {
        int n = i >> 6, c = i & 63;
        sm[n][c] = g_m[(base + n) * 64 + c];
        sh[n][c] = g_out[(base + n) * 64 + c];
    }
    __syncthreads();
    {
        float accI[16], accH[16];
#pragma unroll
        for (int j = 0; j < 16; j++) { accI[j] = 0.f; accH[j] = 0.f; }
        const float* wi = Wih + tid * 64;
        const float* wh = Whh + tid * 64;
        for (int i = 0; i < 64; i++) {
            float a = wi[i], b = wh[i];
#pragma unroll
            for (int j = 0; j < 16; j++) {
                accI[j] += sm[j][i] * a;
                accH[j] += sh[j][i] * b;
            }
        }
        float bi = bih[tid], bh = bhh[tid];
#pragma unroll
        for (int j = 0; j < 16; j++) {
            sgi[j][tid] = accI[j] + bi;
            sgh[j][tid] = accH[j] + bh;
        }
    }
    __syncthreads();
    for (int i = tid; i < 1024; i += 192) {
        int n = i >> 6, c = i & 63;
        float r = sigmoidf_(sgi[n][c] + sgh[n][c]);
        float z = sigmoidf_(sgi[n][64 + c] + sgh[n][64 + c]);
        float nn2 = tanhf(sgi[n][128 + c] + r * sgh[n][128 + c]);
        float hnew = (1.f - z) * nn2 + z * sh[n][c];
        g_out[(base + n) * 64 + c] = hnew;
    }
}

// ---------------- Set2Set LSTM cell (per graph) --------------------------
__global__ __launch_bounds__(256) void k_lstm(const float* __restrict__ Wih,
                                              const float* __restrict__ Whh,
                                              const float* __restrict__ bih,
                                              const float* __restrict__ bhh) {
    int g = blockIdx.x, j = threadIdx.x;
    __shared__ float sq[128], sh[64], sg[256];
    if (j < 128) sq[j] = g_qstar[g * 128 + j];
    else if (j < 192) sh[j - 128] = g_hl[g * 64 + j - 128];
    __syncthreads();
    float acc = bih[j] + bhh[j];
    const float* wi = Wih + j * 128;
#pragma unroll 8
    for (int k = 0; k < 128; k++) acc += sq[k] * wi[k];
    const float* wh = Whh + j * 64;
#pragma unroll 8
    for (int k = 0; k < 64; k++) acc += sh[k] * wh[k];
    sg[j] = acc;
    __syncthreads();
    if (j < 64) {
        float i_ = sg[j], f_ = sg[64 + j], gg = sg[128 + j], o_ = sg[192 + j];
        float c = sigmoidf_(f_) * g_cl[g * 64 + j] + sigmoidf_(i_) * tanhf(gg);
        float h = sigmoidf_(o_) * tanhf(c);
        g_cl[g * 64 + j] = c;
        g_hl[g * 64 + j] = h;
    }
}

// ---------------- Set2Set attention + readout (per graph, contiguous) ----
__global__ __launch_bounds__(64) void k_attn() {
    int g = blockIdx.x, t = threadIdx.x;
    int s = g_gptr[g], e2 = g_gptr[g + 1];
    __shared__ float sq[64], red[64];
    sq[t] = g_hl[g * 64 + t];
    __syncthreads();
    float mx = -3.0e38f;
    for (int n = s + t; n < e2; n += 64) {
        const float* orow = g_out + (size_t)n * 64;
        float acc = 0.f;
#pragma unroll
        for (int i = 0; i < 64; i++) acc += orow[i] * sq[i];
        g_e[n] = acc;
        mx = fmaxf(mx, acc);
    }
    red[t] = mx; __syncthreads();
    for (int st = 32; st > 0; st >>= 1) {
        if (t < st) red[t] = fmaxf(red[t], red[t + st]);
        __syncthreads();
    }
    mx = red[0]; __syncthreads();
    float den = 0.f;
    for (int n = s + t; n < e2; n += 64) {
        float ex = expf(g_e[n] - mx);
        g_e[n] = ex;
        den += ex;
    }
    red[t] = den; __syncthreads();
    for (int st = 32; st > 0; st >>= 1) {
        if (t < st) red[t] += red[t + st];
        __syncthreads();
    }
    den = red[0]; __syncthreads();
    float r = 0.f;
    for (int n = s; n < e2; n++) r += g_e[n] * g_out[(size_t)n * 64 + t];
    if (e2 > s) r /= den;
    g_qstar[g * 128 + t] = sq[t];
    g_qstar[g * 128 + 64 + t] = r;
}

// ---------------- final MLP head -----------------------------------------
__global__ __launch_bounds__(128) void k_final(const float* __restrict__ fc1W,
                                               const float* __restrict__ fc1b,
                                               const float* __restrict__ fc2W,
                                               const float* __restrict__ fc2b,
                                               float* __restrict__ outp) {
    int g = blockIdx.x, j = threadIdx.x;
    __shared__ float sq[128], red[128];
    sq[j] = g_qstar[g * 128 + j];
    __syncthreads();
    float acc = fc1b[j];
    const float* w = fc1W + j * 128;
#pragma unroll 8
    for (int k = 0; k < 128; k++) acc += sq[k] * w[k];
    red[j] = fmaxf(acc, 0.f) * fc2W[j];
    __syncthreads();
    for (int st = 64; st > 0; st >>= 1) {
        if (j < st) red[j] += red[j + st];
        __syncthreads();
    }
    if (j == 0) outp[g] = red[0] + fc2b[0];
}

// ---------------- host: launch sequence ----------------------------------
extern "C" void kernel_launch(void* const* d_in, const int* in_sizes, int n_in,
                              void* d_out, int out_size) {
    const float* x       = (const float*)d_in[0];
    const int*   ei      = (const int*)d_in[1];
    const float* ea      = (const float*)d_in[2];
    const int*   batch   = (const int*)d_in[3];
    const float* lin0_W  = (const float*)d_in[4];
    const float* lin0_b  = (const float*)d_in[5];
    const float* e1_W    = (const float*)d_in[6];
    const float* e1_b    = (const float*)d_in[7];
    const float* e2_W    = (const float*)d_in[8];
    const float* e2_b    = (const float*)d_in[9];
    const float* root_W  = (const float*)d_in[10];
    const float* conv_b  = (const float*)d_in[11];
    const float* gru_Wih = (const float*)d_in[12];
    const float* gru_Whh = (const float*)d_in[13];
    const float* gru_bih = (const float*)d_in[14];
    const float* gru_bhh = (const float*)d_in[15];
    const float* lstm_Wih = (const float*)d_in[16];
    const float* lstm_Whh = (const float*)d_in[17];
    const float* lstm_bih = (const float*)d_in[18];
    const float* lstm_bhh = (const float*)d_in[19];
    const float* fc1_W   = (const float*)d_in[20];
    const float* fc1_b   = (const float*)d_in[21];
    const float* fc2_W   = (const float*)d_in[22];
    const float* fc2_b   = (const float*)d_in[23];
    float* outp = (float*)d_out;

    static bool attr_set = false;
    const int WG_SMEM = 131072 + 128 * STG_STRIDE;   // 165,888 B
    if (!attr_set) {
        cudaFuncSetAttribute(k_wgemm_tc, cudaFuncAttributeMaxDynamicSharedMemorySize, WG_SMEM);
        attr_set = true;
    }

    // k_wgemm_tc is launch #4 — the position ncu's -s 5 -c 1 window captured
    // in rounds 2 and 4 (k_zero_pre both times).
    k_lin0<<<(NN * DD) / 256, 256>>>(x, lin0_W, lin0_b);
    k_edge1<<<(NE * 128) / 256, 256>>>(ea, e1_W, e1_b);
    k_e2split<<<(4096 * 128) / 256, 256>>>(e2_W);
    k_wgemm_tc<<<NE / 128, 256, WG_SMEM>>>(e2_b);
    k_zero_pre<<<NN / 256, 256>>>();
    k_gcnt<<<NN / 256, 256>>>(batch);
    k_cnt<<<NE / 256, 256>>>(ei);
    k_scan<<<1, NB>>>();

    for (int it = 0; it < 3; it++) {
        k_zero_agg<<<(NN * DD) / 256, 256>>>();
        k_msg<<<NE / 4, 256>>>(ei);
        k_prem<<<NN / 32, 256>>>(root_W, conv_b);
        k_gru<<<NN / 16, 192>>>(gru_Wih, gru_Whh, gru_bih, gru_bhh);
    }

    k_zero_s2s<<<(NB * 128) / 256, 256>>>();
    for (int st = 0; st < 3; st++) {
        k_lstm<<<NB, 256>>>(lstm_Wih, lstm_Whh, lstm_bih, lstm_bhh);
        k_attn<<<NB, 64>>>();
    }
    k_final<<<NB, 128>>>(fc1_W, fc1_b, fc2_W, fc2_b, outp);
}